// round 11
// baseline (speedup 1.0000x reference)
#include <cuda_runtime.h>
#include <cuda_bf16.h>
#include <cstdint>
typedef unsigned long long ULL;

__device__ float2 g_A[16*64*256*32];   // [bc][h][ky]
__device__ float2 g_X[16*32*32*64];    // [b][mode][c]
__device__ float2 g_M[16*64*32*32];    // [bo][kx][ky]
__device__ float2 g_T[16*64*256*32];   // [bo][h][ky]
__device__ float2 g_Wt[1024*64*64];    // [m][c][o]
__device__ ulonglong2 g_t2[256];       // ((c,c),(s,-s))
__device__ ulonglong2 g_t4[256];       // ((c,s),(-s,c))
__device__ __nv_bfloat16 g_B5h[256*64], g_B5l[256*64];  // [w][k] k<32:cos, k>=32:-sin
__device__ __nv_bfloat16 g_B1h[64*256], g_B1l[64*256];  // [kcol][w] cos/256 | -sin/256

__device__ __forceinline__ ULL ff2(ULL a, ULL b, ULL c) {
    ULL d; asm("fma.rn.f32x2 %0, %1, %2, %3;" : "=l"(d) : "l"(a), "l"(b), "l"(c)); return d;
}
__device__ __forceinline__ ULL add2(ULL a, ULL b) {
    ULL d; asm("add.rn.f32x2 %0, %1, %2;" : "=l"(d) : "l"(a), "l"(b)); return d;
}
__device__ __forceinline__ ULL sub2(ULL a, ULL b) {
    ULL d; asm("sub.rn.f32x2 %0, %1, %2;" : "=l"(d) : "l"(a), "l"(b)); return d;
}
__device__ __forceinline__ ULL mul2(ULL a, ULL b) {
    ULL d; asm("mul.rn.f32x2 %0, %1, %2;" : "=l"(d) : "l"(a), "l"(b)); return d;
}
__device__ __forceinline__ ULL pack2(float x, float y) {
    ULL d; asm("mov.b64 %0, {%1, %2};" : "=l"(d) : "f"(x), "f"(y)); return d;
}
__device__ __forceinline__ float2 unpack2(ULL v) {
    float2 r; asm("mov.b64 {%0, %1}, %2;" : "=f"(r.x), "=f"(r.y) : "l"(v)); return r;
}
__device__ __forceinline__ void mma_bf16(float d[4], uint32_t a0, uint32_t a1,
                                         uint32_t a2, uint32_t a3,
                                         uint32_t b0, uint32_t b1) {
    asm("mma.sync.aligned.m16n8k16.row.col.f32.bf16.bf16.f32 "
        "{%0,%1,%2,%3}, {%4,%5,%6,%7}, {%8,%9}, {%0,%1,%2,%3};"
        : "+f"(d[0]), "+f"(d[1]), "+f"(d[2]), "+f"(d[3])
        : "r"(a0), "r"(a1), "r"(a2), "r"(a3), "r"(b0), "r"(b1));
}

__global__ void k_tw() {
    int k = threadIdx.x;
    double a = 6.283185307179586476925286766559 * k / 256.0;
    float c = (float)cos(a), s = (float)sin(a);
    g_t2[k] = make_ulonglong2(pack2(c, c), pack2(s, -s));
    g_t4[k] = make_ulonglong2(pack2(c, s), pack2(-s, c));
}
__global__ void k_tw2() {           // grid 256 (w), 64 thr (k)
    int w = blockIdx.x, k = threadIdx.x;
    double a = 6.283185307179586476925286766559 * ((k & 31) * w) / 256.0;
    float v = (k < 32) ? (float)cos(a) : -(float)sin(a);
    __nv_bfloat16 hi = __float2bfloat16(v);
    g_B5h[w * 64 + k] = hi;
    g_B5l[w * 64 + k] = __float2bfloat16(v - __bfloat162float(hi));
}
__global__ void k_tw1() {           // grid 64 (kcol), 256 thr (w)
    int kc = blockIdx.x, w = threadIdx.x;
    double a = 6.283185307179586476925286766559 * ((kc & 31) * w) / 256.0;
    float v = ((kc < 32) ? (float)cos(a) : -(float)sin(a)) * (1.0f / 256.0f);
    __nv_bfloat16 hi = __float2bfloat16(v);
    g_B1h[kc * 256 + w] = hi;
    g_B1l[kc * 256 + w] = __float2bfloat16(v - __bfloat162float(hi));
}

// Weight transpose: [c][o][m] -> g_Wt[m][c][o].
__global__ __launch_bounds__(256) void k_wt(const float* __restrict__ wr,
                                            const float* __restrict__ wi) {
    __shared__ float2 st[32][33];
    int co0 = blockIdx.x * 32, m0 = blockIdx.y * 32;
    for (int i = threadIdx.x; i < 1024; i += 256) {
        int lco = i >> 5, lm = i & 31;
        size_t src = (size_t)(co0 + lco) * 1024 + m0 + lm;
        st[lco][lm] = make_float2(wr[src], wi[src]);
    }
    __syncthreads();
    for (int i = threadIdx.x; i < 1024; i += 256) {
        int lm = i >> 5, lco = i & 31;
        g_Wt[(size_t)(m0 + lm) * 4096 + co0 + lco] = st[lco][lm];
    }
}

// K1 (tensor core): A[h,ky] = sum_w x[h,w] * E[kcol,w], bf16 2-split.
// grid (1024 bc, 2 h-half of 128). block 256 = 8 warps (m-tiles of 16h), N=64.
__global__ __launch_bounds__(256) void k_fwdW(const float* __restrict__ x) {
    __shared__ uint32_t Bs[2][64][128];  // [split][kcol][w-b32], 64 KB
    __shared__ uint32_t As[2][128][32];  // [split][h][w-b32 per phase], 32 KB
    int bc = blockIdx.x, h0 = blockIdx.y * 128;
    int tid = threadIdx.x;
    const float* xr = x + (size_t)bc * 65536 + (size_t)h0 * 256;

    for (int i = tid; i < 16384; i += 256) {   // stage B (hi|lo)
        int sp = i >> 13, r = (i >> 7) & 63, cb = i & 127;
        const __nv_bfloat16* src = sp ? g_B1l : g_B1h;
        Bs[sp][r][cb ^ ((r & 7) << 2)] =
            *reinterpret_cast<const uint32_t*>(&src[r * 256 + cb * 2]);
    }

    int lane = tid & 31, wrp = tid >> 5;
    int gid = lane >> 2, tig = lane & 3;
    float d[8][4];
    #pragma unroll
    for (int nt = 0; nt < 8; nt++)
        { d[nt][0]=0.f; d[nt][1]=0.f; d[nt][2]=0.f; d[nt][3]=0.f; }

    __nv_bfloat16* Ab = reinterpret_cast<__nv_bfloat16*>(As);
    for (int p = 0; p < 4; p++) {
        __syncthreads();
        for (int i = tid; i < 8192; i += 256) {  // stage A phase (128h x 64w)
            int h = i >> 6, wl = i & 63;
            float f = xr[h * 256 + p * 64 + wl];
            __nv_bfloat16 hi = __float2bfloat16(f);
            __nv_bfloat16 lo = __float2bfloat16(f - __bfloat162float(hi));
            int wd = (wl >> 1) ^ ((h & 7) << 2);
            int base = (h * 32 + wd) * 2 + (wl & 1);
            Ab[base] = hi;
            Ab[8192 + base] = lo;
        }
        __syncthreads();
        #pragma unroll
        for (int c = 0; c < 12; c++) {
            int asel = (c >= 8) ? 1 : 0;
            int bsel = (c >= 4 && c < 8) ? 1 : 0;
            int kb = (c & 3) * 8;
            int r0 = wrp * 16 + gid, r1 = r0 + 8;
            uint32_t a0 = As[asel][r0][(kb + tig)     ^ ((r0 & 7) << 2)];
            uint32_t a1 = As[asel][r1][(kb + tig)     ^ ((r1 & 7) << 2)];
            uint32_t a2 = As[asel][r0][(kb + 4 + tig) ^ ((r0 & 7) << 2)];
            uint32_t a3 = As[asel][r1][(kb + 4 + tig) ^ ((r1 & 7) << 2)];
            int kbg = p * 32 + kb;
            #pragma unroll
            for (int nt = 0; nt < 8; nt++) {
                int n = nt * 8 + gid;
                uint32_t b0 = Bs[bsel][n][(kbg + tig)     ^ ((n & 7) << 2)];
                uint32_t b1 = Bs[bsel][n][(kbg + 4 + tig) ^ ((n & 7) << 2)];
                mma_bf16(d[nt], a0, a1, a2, a3, b0, b1);
            }
        }
    }

    // write (re, im) pairs: re = col ky (nt<4), im = col 32+ky (nt+4)
    float2* A = &g_A[(size_t)bc * 8192 + (size_t)h0 * 32];
    int r0 = wrp * 16 + gid;
    #pragma unroll
    for (int nt = 0; nt < 4; nt++) {
        int ky0 = nt * 8 + tig * 2;
        *reinterpret_cast<float4*>(&A[r0 * 32 + ky0]) =
            make_float4(d[nt][0], d[nt+4][0], d[nt][1], d[nt+4][1]);
        *reinterpret_cast<float4*>(&A[(r0 + 8) * 32 + ky0]) =
            make_float4(d[nt][2], d[nt+4][2], d[nt][3], d[nt+4][3]);
    }
}

// K2: fwd H-transform, h-parity fold (unchanged).
__global__ __launch_bounds__(256) void k_fwdH() {
    __shared__ ULL sP[128 * 32], sQ[128 * 32];
    __shared__ ulonglong2 st2[256];
    int bc = blockIdx.x;
    const ULL* A = reinterpret_cast<const ULL*>(&g_A[(size_t)bc * 8192]);
    if (threadIdx.x < 256) st2[threadIdx.x] = g_t2[threadIdx.x];
    for (int i = threadIdx.x; i < 4096; i += 256) {
        ULL a = A[i], b = A[i + 4096];
        sP[i] = add2(a, b); sQ[i] = sub2(a, b);
    }
    __syncthreads();
    int lane = threadIdx.x & 31, wrp = threadIdx.x >> 5;
    int par = wrp & 1, base = par + 8 * (wrp >> 1);
    const ULL* sD = par ? sQ : sP;
    ULL acc[4]; int idx[4]; int kxv[4];
    #pragma unroll
    for (int t = 0; t < 4; t++) { acc[t] = 0; idx[t] = 0; kxv[t] = base + 2 * t; }
    #pragma unroll 4
    for (int h = 0; h < 128; h++) {
        ULL dv = sD[h * 32 + lane];
        float2 f = unpack2(dv);
        ULL dsn = pack2(f.y, f.x);
        #pragma unroll
        for (int t = 0; t < 4; t++) {
            ulonglong2 tw = st2[idx[t]];
            acc[t] = ff2(dv, tw.x, ff2(dsn, tw.y, acc[t]));
            idx[t] = (idx[t] + kxv[t]) & 255;
        }
    }
    int b = bc >> 6, c = bc & 63;
    #pragma unroll
    for (int t = 0; t < 4; t++)
        g_X[((size_t)b * 1024 + kxv[t] * 32 + lane) * 64 + c] = unpack2(acc[t]);
}

// K3: channel mix, coalesced weights.
__global__ __launch_bounds__(256) void k_mix() {
    int m = blockIdx.x;
    __shared__ float2 Ws[4096], Xs[1024];
    for (int i = threadIdx.x; i < 4096; i += 256)
        Ws[i] = g_Wt[(size_t)m * 4096 + i];
    for (int i = threadIdx.x; i < 1024; i += 256)
        Xs[i] = g_X[((size_t)(i >> 6) * 1024 + m) * 64 + (i & 63)];
    __syncthreads();
    #pragma unroll
    for (int k = 0; k < 4; k++) {
        int id = threadIdx.x + k * 256, b = id >> 6, o = id & 63;
        float ar = 0.f, ai = 0.f;
        #pragma unroll 8
        for (int c = 0; c < 64; c++) {
            float2 X = Xs[b * 64 + c], W = Ws[c * 64 + o];
            ar = fmaf(X.x, W.x, fmaf(-X.y, W.y, ar));
            ai = fmaf(X.x, W.y, fmaf( X.y, W.x, ai));
        }
        g_M[((size_t)b * 64 + o) * 1024 + m] = make_float2(ar, ai);
    }
}

// K4: inv H-transform, kx-parity fold (unchanged).
__global__ __launch_bounds__(256) void k_invH() {
    __shared__ ULL Ms[1024];
    __shared__ ulonglong2 st4[256];
    int bo = blockIdx.x;
    const ULL* M = reinterpret_cast<const ULL*>(&g_M[(size_t)bo * 1024]);
    if (threadIdx.x < 256) st4[threadIdx.x] = g_t4[threadIdx.x];
    for (int i = threadIdx.x; i < 1024; i += 256) Ms[i] = M[i];
    __syncthreads();
    int lane = threadIdx.x & 31, wrp = threadIdx.x >> 5, hb = wrp * 16;
    ULL E[16], O[16]; int idx[16];
    #pragma unroll
    for (int j = 0; j < 16; j++) { E[j] = 0; O[j] = 0; idx[j] = 0; }
    #pragma unroll
    for (int kx = 0; kx < 32; kx++) {
        float2 f = unpack2(Ms[kx * 32 + lane]);
        ULL mrr = pack2(f.x, f.x), mii = pack2(f.y, f.y);
        #pragma unroll
        for (int j = 0; j < 16; j++) {
            ulonglong2 tw = st4[idx[j]];
            if (kx & 1) O[j] = ff2(mrr, tw.x, ff2(mii, tw.y, O[j]));
            else        E[j] = ff2(mrr, tw.x, ff2(mii, tw.y, E[j]));
            idx[j] = (idx[j] + hb + j) & 255;
        }
    }
    float sv = (lane == 0 ? 1.f : 2.f) / 256.f;
    ULL s2 = pack2(sv, sv);
    ULL* T = reinterpret_cast<ULL*>(&g_T[(size_t)bo * 8192]);
    #pragma unroll
    for (int j = 0; j < 16; j++) {
        T[(hb + j) * 32 + lane]       = mul2(add2(E[j], O[j]), s2);
        T[(hb + j + 128) * 32 + lane] = mul2(sub2(E[j], O[j]), s2);
    }
}

// K5: tensor-core inverse W (unchanged from R10).
__global__ __launch_bounds__(256) void k_invW(float* __restrict__ out) {
    __shared__ uint32_t As[2][64][32];
    __shared__ uint32_t Bs[2][128][32];
    int bog = blockIdx.x, w0 = blockIdx.y * 128, h0 = blockIdx.z * 64;
    int tid = threadIdx.x;

    for (int i = tid; i < 4096; i += 256) {
        int w = i >> 5, cb = i & 31;
        int sc = cb ^ ((w & 7) << 2);
        Bs[0][w][sc] = *reinterpret_cast<const uint32_t*>(&g_B5h[(w0 + w) * 64 + cb * 2]);
        Bs[1][w][sc] = *reinterpret_cast<const uint32_t*>(&g_B5l[(w0 + w) * 64 + cb * 2]);
    }

    int lane = tid & 31, wrp = tid >> 5;
    int gid = lane >> 2, tig = lane & 3;
    int wm = wrp & 1, wn = wrp >> 1;

    for (int s = 0; s < 4; s++) {
        int bo = bog * 4 + s;
        __syncthreads();
        const float2* T = &g_T[((size_t)bo * 256 + h0) * 32];
        __nv_bfloat16* Ab = reinterpret_cast<__nv_bfloat16*>(As);
        for (int i = tid; i < 2048; i += 256) {
            int h = i >> 5, ky = i & 31;
            float2 v = T[i];
            #pragma unroll
            for (int q = 0; q < 2; q++) {
                int k = ky + q * 32;
                float f = q ? v.y : v.x;
                __nv_bfloat16 hi = __float2bfloat16(f);
                __nv_bfloat16 lo = __float2bfloat16(f - __bfloat162float(hi));
                int wd = (k >> 1) ^ ((h & 7) << 2);
                int base = (h * 32 + wd) * 2 + (k & 1);
                Ab[base] = hi;
                Ab[4096 + base] = lo;
            }
        }
        __syncthreads();

        float d[2][4][4];
        #pragma unroll
        for (int mt = 0; mt < 2; mt++)
            #pragma unroll
            for (int nt = 0; nt < 4; nt++)
                { d[mt][nt][0]=0.f; d[mt][nt][1]=0.f; d[mt][nt][2]=0.f; d[mt][nt][3]=0.f; }

        #pragma unroll
        for (int c = 0; c < 12; c++) {
            int asel = (c >= 8) ? 1 : 0;
            int bsel = (c >= 4 && c < 8) ? 1 : 0;
            int kb = (c & 3) * 8;
            uint32_t a[2][4];
            #pragma unroll
            for (int mt = 0; mt < 2; mt++) {
                int r0 = wm * 32 + mt * 16 + gid, r1 = r0 + 8;
                a[mt][0] = As[asel][r0][(kb + tig)     ^ ((r0 & 7) << 2)];
                a[mt][1] = As[asel][r1][(kb + tig)     ^ ((r1 & 7) << 2)];
                a[mt][2] = As[asel][r0][(kb + 4 + tig) ^ ((r0 & 7) << 2)];
                a[mt][3] = As[asel][r1][(kb + 4 + tig) ^ ((r1 & 7) << 2)];
            }
            #pragma unroll
            for (int nt = 0; nt < 4; nt++) {
                int wr_ = wn * 32 + nt * 8 + gid;
                uint32_t b0 = Bs[bsel][wr_][(kb + tig)     ^ ((wr_ & 7) << 2)];
                uint32_t b1 = Bs[bsel][wr_][(kb + 4 + tig) ^ ((wr_ & 7) << 2)];
                #pragma unroll
                for (int mt = 0; mt < 2; mt++)
                    mma_bf16(d[mt][nt], a[mt][0], a[mt][1], a[mt][2], a[mt][3], b0, b1);
            }
        }
        float* op = out + (size_t)bo * 65536 + (size_t)h0 * 256 + w0;
        #pragma unroll
        for (int mt = 0; mt < 2; mt++) {
            int r0 = wm * 32 + mt * 16 + gid;
            #pragma unroll
            for (int nt = 0; nt < 4; nt++) {
                int cc = wn * 32 + nt * 8 + tig * 2;
                *reinterpret_cast<float2*>(op + (size_t)r0 * 256 + cc) =
                    make_float2(d[mt][nt][0], d[mt][nt][1]);
                *reinterpret_cast<float2*>(op + (size_t)(r0 + 8) * 256 + cc) =
                    make_float2(d[mt][nt][2], d[mt][nt][3]);
            }
        }
    }
}

extern "C" void kernel_launch(void* const* d_in, const int* in_sizes, int n_in,
                              void* d_out, int out_size) {
    (void)in_sizes; (void)n_in; (void)out_size;
    const float* x  = (const float*)d_in[0];
    const float* wr = (const float*)d_in[1];
    const float* wi = (const float*)d_in[2];
    float* out = (float*)d_out;

    k_tw  <<<1, 256>>>();
    k_tw2 <<<256, 64>>>();
    k_tw1 <<<64, 256>>>();
    k_wt  <<<dim3(128, 32), 256>>>(wr, wi);
    k_fwdW<<<dim3(1024, 2), 256>>>(x);
    k_fwdH<<<1024, 256>>>();
    k_mix <<<1024, 256>>>();
    k_invH<<<1024, 256>>>();
    k_invW<<<dim3(256, 2, 4), 256>>>(out);
}

// round 14
// speedup vs baseline: 1.2501x; 1.2501x over previous
#include <cuda_runtime.h>
#include <cuda_bf16.h>
#include <cstdint>
typedef unsigned long long ULL;

__device__ float2 g_A[16*64*256*32];   // [bc][h][ky]
__device__ float2 g_X[16*32*32*64];    // [b][mode][c]
__device__ float2 g_M[16*64*32*32];    // [bo][kx][ky]
__device__ float2 g_T[16*64*256*32];   // [bo][h][ky]
__device__ float2 g_Wt[1024*64*64];    // [m][c][o]
__device__ ULL        g_t1[256];       // (cos, -sin)
__device__ ulonglong2 g_t2[256];       // ((c,c),(s,-s))
__device__ ulonglong2 g_t4[256];       // ((c,s),(-s,c))
__device__ __nv_bfloat16 g_B5h[256*64], g_B5l[256*64];  // [w][k] k<32:cos else -sin

__device__ __forceinline__ ULL ff2(ULL a, ULL b, ULL c) {
    ULL d; asm("fma.rn.f32x2 %0, %1, %2, %3;" : "=l"(d) : "l"(a), "l"(b), "l"(c)); return d;
}
__device__ __forceinline__ ULL add2(ULL a, ULL b) {
    ULL d; asm("add.rn.f32x2 %0, %1, %2;" : "=l"(d) : "l"(a), "l"(b)); return d;
}
__device__ __forceinline__ ULL sub2(ULL a, ULL b) {
    ULL d; asm("sub.rn.f32x2 %0, %1, %2;" : "=l"(d) : "l"(a), "l"(b)); return d;
}
__device__ __forceinline__ ULL mul2(ULL a, ULL b) {
    ULL d; asm("mul.rn.f32x2 %0, %1, %2;" : "=l"(d) : "l"(a), "l"(b)); return d;
}
__device__ __forceinline__ ULL pack2(float x, float y) {
    ULL d; asm("mov.b64 %0, {%1, %2};" : "=l"(d) : "f"(x), "f"(y)); return d;
}
__device__ __forceinline__ float2 unpack2(ULL v) {
    float2 r; asm("mov.b64 {%0, %1}, %2;" : "=f"(r.x), "=f"(r.y) : "l"(v)); return r;
}
__device__ __forceinline__ void mma_bf16(float d[4], uint32_t a0, uint32_t a1,
                                         uint32_t a2, uint32_t a3,
                                         uint32_t b0, uint32_t b1) {
    asm("mma.sync.aligned.m16n8k16.row.col.f32.bf16.bf16.f32 "
        "{%0,%1,%2,%3}, {%4,%5,%6,%7}, {%8,%9}, {%0,%1,%2,%3};"
        : "+f"(d[0]), "+f"(d[1]), "+f"(d[2]), "+f"(d[3])
        : "r"(a0), "r"(a1), "r"(a2), "r"(a3), "r"(b0), "r"(b1));
}

__global__ void k_tw() {
    int k = threadIdx.x;
    double a = 6.283185307179586476925286766559 * k / 256.0;
    float c = (float)cos(a), s = (float)sin(a);
    g_t1[k] = pack2(c, -s);
    g_t2[k] = make_ulonglong2(pack2(c, c), pack2(s, -s));
    g_t4[k] = make_ulonglong2(pack2(c, s), pack2(-s, c));
}
__global__ void k_tw2() {
    int w = blockIdx.x, k = threadIdx.x;
    double a = 6.283185307179586476925286766559 * ((k & 31) * w) / 256.0;
    float v = (k < 32) ? (float)cos(a) : -(float)sin(a);
    __nv_bfloat16 hi = __float2bfloat16(v);
    g_B5h[w * 64 + k] = hi;
    g_B5l[w * 64 + k] = __float2bfloat16(v - __bfloat162float(hi));
}
__global__ __launch_bounds__(256) void k_wt(const float* __restrict__ wr,
                                            const float* __restrict__ wi) {
    __shared__ float2 st[32][33];
    int co0 = blockIdx.x * 32, m0 = blockIdx.y * 32;
    for (int i = threadIdx.x; i < 1024; i += 256) {
        int lco = i >> 5, lm = i & 31;
        size_t src = (size_t)(co0 + lco) * 1024 + m0 + lm;
        st[lco][lm] = make_float2(wr[src], wi[src]);
    }
    __syncthreads();
    for (int i = threadIdx.x; i < 1024; i += 256) {
        int lm = i >> 5, lco = i & 31;
        g_Wt[(size_t)(m0 + lm) * 4096 + co0 + lco] = st[lco][lm];
    }
}

// ---------------------------------------------------------------------------
// K1: fwd W, quad fold {w,128-w,128+w,256-w}. grid (1024 bc, 2 h-halves of 128).
// warp -> 4 ky (wrp+8k; parity & ky%4 warp-uniform); thread -> 4 h (lane+32j).
// w staged in 4 phases of <=16 into sE/sO (stride 17 ULL = conflict-free LDS.64).
// ---------------------------------------------------------------------------
__global__ __launch_bounds__(256) void k_fwdW(const float* __restrict__ x) {
    __shared__ __align__(16) char buf[128 * 17 * 8 * 2];  // sE|sO, reused as sRes
    __shared__ ULL st1[256];
    __shared__ float4 sSp[128];
    ULL* sE = reinterpret_cast<ULL*>(buf);
    ULL* sO = sE + 128 * 17;
    int bc = blockIdx.x, h0 = blockIdx.y * 128, tid = threadIdx.x;
    int lane = tid & 31, wrp = tid >> 5;
    if (tid < 256) st1[tid] = g_t1[tid];
    const float* xr = x + (size_t)bc * 65536 + (size_t)h0 * 256;
    for (int i = tid; i < 128; i += 256) {
        const float* row = xr + i * 256;
        sSp[i] = make_float4(row[0], row[64], row[128], row[192]);
    }
    int w3 = wrp & 3, par = wrp & 1;
    float c64 = (w3 == 0) ? 1.f : ((w3 == 2) ? -1.f : 0.f);
    float s64 = (w3 == 1) ? 1.f : ((w3 == 3) ? -1.f : 0.f);
    float sg1 = par ? -1.f : 1.f;
    int kyv[4];
    #pragma unroll
    for (int k = 0; k < 4; k++) kyv[k] = wrp + 8 * k;
    __syncthreads();
    ULL acc[4][4];
    #pragma unroll
    for (int j = 0; j < 4; j++) {
        float4 sp = sSp[lane + 32 * j];
        ULL a = pack2(sp.x + sg1 * sp.z + c64 * (sp.y + sp.w), -s64 * (sp.y - sp.w));
        #pragma unroll
        for (int k = 0; k < 4; k++) acc[k][j] = a;
    }
    const ULL* sD = par ? sO : sE;

    for (int ph = 0; ph < 4; ph++) {
        int wb = ph * 16 + 1, nw = (ph == 3) ? 15 : 16;
        __syncthreads();
        for (int i = tid; i < 2048; i += 256) {
            int h = i >> 4, wl = i & 15;
            if (wl < nw) {
                int w = wb + wl;
                const float* row = xr + h * 256;
                float xa = row[w], xb = row[256 - w], xm = row[128 - w], xp = row[128 + w];
                float ap = xa + xb, am = xa - xb, bp = xm + xp, bm = xp - xm;
                sE[h * 17 + wl] = pack2(ap + bp, am + bm);
                sO[h * 17 + wl] = pack2(ap - bp, am - bm);
            }
        }
        __syncthreads();
        int idx[4];
        #pragma unroll
        for (int k = 0; k < 4; k++) idx[k] = (kyv[k] * wb) & 255;
        #pragma unroll 4
        for (int wl = 0; wl < nw; wl++) {
            ULL d0 = sD[lane * 17 + wl];
            ULL d1 = sD[(lane + 32) * 17 + wl];
            ULL d2 = sD[(lane + 64) * 17 + wl];
            ULL d3 = sD[(lane + 96) * 17 + wl];
            #pragma unroll
            for (int k = 0; k < 4; k++) {
                ULL t = st1[idx[k]];
                acc[k][0] = ff2(d0, t, acc[k][0]);
                acc[k][1] = ff2(d1, t, acc[k][1]);
                acc[k][2] = ff2(d2, t, acc[k][2]);
                acc[k][3] = ff2(d3, t, acc[k][3]);
                idx[k] = (idx[k] + kyv[k]) & 255;
            }
        }
    }
    __syncthreads();
    ULL* sRes = reinterpret_cast<ULL*>(buf);
    ULL s2 = pack2(1.f / 256.f, 1.f / 256.f);
    #pragma unroll
    for (int k = 0; k < 4; k++)
        #pragma unroll
        for (int j = 0; j < 4; j++)
            sRes[(lane + 32 * j) * 33 + kyv[k]] = mul2(acc[k][j], s2);
    __syncthreads();
    ULL* Ao = reinterpret_cast<ULL*>(&g_A[(size_t)bc * 8192 + (size_t)h0 * 32]);
    for (int i = tid; i < 4096; i += 256)
        Ao[i] = sRes[(i >> 5) * 33 + (i & 31)];
}

// K2: fwd H, h-parity fold (unchanged from R10/516us baseline).
__global__ __launch_bounds__(256) void k_fwdH() {
    __shared__ ULL sP[128 * 32], sQ[128 * 32];
    __shared__ ulonglong2 st2[256];
    int bc = blockIdx.x;
    const ULL* A = reinterpret_cast<const ULL*>(&g_A[(size_t)bc * 8192]);
    if (threadIdx.x < 256) st2[threadIdx.x] = g_t2[threadIdx.x];
    for (int i = threadIdx.x; i < 4096; i += 256) {
        ULL a = A[i], b = A[i + 4096];
        sP[i] = add2(a, b); sQ[i] = sub2(a, b);
    }
    __syncthreads();
    int lane = threadIdx.x & 31, wrp = threadIdx.x >> 5;
    int par = wrp & 1, base = par + 8 * (wrp >> 1);
    const ULL* sD = par ? sQ : sP;
    ULL acc[4]; int idx[4]; int kxv[4];
    #pragma unroll
    for (int t = 0; t < 4; t++) { acc[t] = 0; idx[t] = 0; kxv[t] = base + 2 * t; }
    #pragma unroll 4
    for (int h = 0; h < 128; h++) {
        ULL dv = sD[h * 32 + lane];
        float2 f = unpack2(dv);
        ULL dsn = pack2(f.y, f.x);
        #pragma unroll
        for (int t = 0; t < 4; t++) {
            ulonglong2 tw = st2[idx[t]];
            acc[t] = ff2(dv, tw.x, ff2(dsn, tw.y, acc[t]));
            idx[t] = (idx[t] + kxv[t]) & 255;
        }
    }
    int b = bc >> 6, c = bc & 63;
    #pragma unroll
    for (int t = 0; t < 4; t++)
        g_X[((size_t)b * 1024 + kxv[t] * 32 + lane) * 64 + c] = unpack2(acc[t]);
}

// K3: channel mix, coalesced weights (unchanged).
__global__ __launch_bounds__(256) void k_mix() {
    int m = blockIdx.x;
    __shared__ float2 Ws[4096], Xs[1024];
    for (int i = threadIdx.x; i < 4096; i += 256)
        Ws[i] = g_Wt[(size_t)m * 4096 + i];
    for (int i = threadIdx.x; i < 1024; i += 256)
        Xs[i] = g_X[((size_t)(i >> 6) * 1024 + m) * 64 + (i & 63)];
    __syncthreads();
    #pragma unroll
    for (int k = 0; k < 4; k++) {
        int id = threadIdx.x + k * 256, b = id >> 6, o = id & 63;
        float ar = 0.f, ai = 0.f;
        #pragma unroll 8
        for (int c = 0; c < 64; c++) {
            float2 X = Xs[b * 64 + c], W = Ws[c * 64 + o];
            ar = fmaf(X.x, W.x, fmaf(-X.y, W.y, ar));
            ai = fmaf(X.x, W.y, fmaf( X.y, W.x, ai));
        }
        g_M[((size_t)b * 64 + o) * 1024 + m] = make_float2(ar, ai);
    }
}

// K4: inv H, kx-parity fold (unchanged).
__global__ __launch_bounds__(256) void k_invH() {
    __shared__ ULL Ms[1024];
    __shared__ ulonglong2 st4[256];
    int bo = blockIdx.x;
    const ULL* M = reinterpret_cast<const ULL*>(&g_M[(size_t)bo * 1024]);
    if (threadIdx.x < 256) st4[threadIdx.x] = g_t4[threadIdx.x];
    for (int i = threadIdx.x; i < 1024; i += 256) Ms[i] = M[i];
    __syncthreads();
    int lane = threadIdx.x & 31, wrp = threadIdx.x >> 5, hb = wrp * 16;
    ULL E[16], O[16]; int idx[16];
    #pragma unroll
    for (int j = 0; j < 16; j++) { E[j] = 0; O[j] = 0; idx[j] = 0; }
    #pragma unroll
    for (int kx = 0; kx < 32; kx++) {
        float2 f = unpack2(Ms[kx * 32 + lane]);
        ULL mrr = pack2(f.x, f.x), mii = pack2(f.y, f.y);
        #pragma unroll
        for (int j = 0; j < 16; j++) {
            ulonglong2 tw = st4[idx[j]];
            if (kx & 1) O[j] = ff2(mrr, tw.x, ff2(mii, tw.y, O[j]));
            else        E[j] = ff2(mrr, tw.x, ff2(mii, tw.y, E[j]));
            idx[j] = (idx[j] + hb + j) & 255;
        }
    }
    float sv = (lane == 0 ? 1.f : 2.f) / 256.f;
    ULL s2 = pack2(sv, sv);
    ULL* T = reinterpret_cast<ULL*>(&g_T[(size_t)bo * 8192]);
    #pragma unroll
    for (int j = 0; j < 16; j++) {
        T[(hb + j) * 32 + lane]       = mul2(add2(E[j], O[j]), s2);
        T[(hb + j + 128) * 32 + lane] = mul2(sub2(E[j], O[j]), s2);
    }
}

// K5: inverse W via mma.sync bf16 2-split (unchanged from R10).
__global__ __launch_bounds__(256) void k_invW(float* __restrict__ out) {
    __shared__ uint32_t As[2][64][32];
    __shared__ uint32_t Bs[2][128][32];
    int bog = blockIdx.x, w0 = blockIdx.y * 128, h0 = blockIdx.z * 64;
    int tid = threadIdx.x;
    for (int i = tid; i < 4096; i += 256) {
        int w = i >> 5, cb = i & 31;
        int sc = cb ^ ((w & 7) << 2);
        Bs[0][w][sc] = *reinterpret_cast<const uint32_t*>(&g_B5h[(w0 + w) * 64 + cb * 2]);
        Bs[1][w][sc] = *reinterpret_cast<const uint32_t*>(&g_B5l[(w0 + w) * 64 + cb * 2]);
    }
    int lane = tid & 31, wrp = tid >> 5;
    int gid = lane >> 2, tig = lane & 3;
    int wm = wrp & 1, wn = wrp >> 1;
    for (int s = 0; s < 4; s++) {
        int bo = bog * 4 + s;
        __syncthreads();
        const float2* T = &g_T[((size_t)bo * 256 + h0) * 32];
        __nv_bfloat16* Ab = reinterpret_cast<__nv_bfloat16*>(As);
        for (int i = tid; i < 2048; i += 256) {
            int h = i >> 5, ky = i & 31;
            float2 v = T[i];
            #pragma unroll
            for (int q = 0; q < 2; q++) {
                int k = ky + q * 32;
                float f = q ? v.y : v.x;
                __nv_bfloat16 hi = __float2bfloat16(f);
                __nv_bfloat16 lo = __float2bfloat16(f - __bfloat162float(hi));
                int wd = (k >> 1) ^ ((h & 7) << 2);
                int base = (h * 32 + wd) * 2 + (k & 1);
                Ab[base] = hi;
                Ab[4096 + base] = lo;
            }
        }
        __syncthreads();
        float d[2][4][4];
        #pragma unroll
        for (int mt = 0; mt < 2; mt++)
            #pragma unroll
            for (int nt = 0; nt < 4; nt++)
                { d[mt][nt][0]=0.f; d[mt][nt][1]=0.f; d[mt][nt][2]=0.f; d[mt][nt][3]=0.f; }
        #pragma unroll
        for (int c = 0; c < 12; c++) {
            int asel = (c >= 8) ? 1 : 0;
            int bsel = (c >= 4 && c < 8) ? 1 : 0;
            int kb = (c & 3) * 8;
            uint32_t a[2][4];
            #pragma unroll
            for (int mt = 0; mt < 2; mt++) {
                int r0 = wm * 32 + mt * 16 + gid, r1 = r0 + 8;
                a[mt][0] = As[asel][r0][(kb + tig)     ^ ((r0 & 7) << 2)];
                a[mt][1] = As[asel][r1][(kb + tig)     ^ ((r1 & 7) << 2)];
                a[mt][2] = As[asel][r0][(kb + 4 + tig) ^ ((r0 & 7) << 2)];
                a[mt][3] = As[asel][r1][(kb + 4 + tig) ^ ((r1 & 7) << 2)];
            }
            #pragma unroll
            for (int nt = 0; nt < 4; nt++) {
                int wr_ = wn * 32 + nt * 8 + gid;
                uint32_t b0 = Bs[bsel][wr_][(kb + tig)     ^ ((wr_ & 7) << 2)];
                uint32_t b1 = Bs[bsel][wr_][(kb + 4 + tig) ^ ((wr_ & 7) << 2)];
                #pragma unroll
                for (int mt = 0; mt < 2; mt++)
                    mma_bf16(d[mt][nt], a[mt][0], a[mt][1], a[mt][2], a[mt][3], b0, b1);
            }
        }
        float* op = out + (size_t)bo * 65536 + (size_t)h0 * 256 + w0;
        #pragma unroll
        for (int mt = 0; mt < 2; mt++) {
            int r0 = wm * 32 + mt * 16 + gid;
            #pragma unroll
            for (int nt = 0; nt < 4; nt++) {
                int cc = wn * 32 + nt * 8 + tig * 2;
                *reinterpret_cast<float2*>(op + (size_t)r0 * 256 + cc) =
                    make_float2(d[mt][nt][0], d[mt][nt][1]);
                *reinterpret_cast<float2*>(op + (size_t)(r0 + 8) * 256 + cc) =
                    make_float2(d[mt][nt][2], d[mt][nt][3]);
            }
        }
    }
}

extern "C" void kernel_launch(void* const* d_in, const int* in_sizes, int n_in,
                              void* d_out, int out_size) {
    (void)in_sizes; (void)n_in; (void)out_size;
    const float* x  = (const float*)d_in[0];
    const float* wr = (const float*)d_in[1];
    const float* wi = (const float*)d_in[2];
    float* out = (float*)d_out;

    k_tw  <<<1, 256>>>();
    k_tw2 <<<256, 64>>>();
    k_wt  <<<dim3(128, 32), 256>>>(wr, wi);
    k_fwdW<<<dim3(1024, 2), 256>>>(x);
    k_fwdH<<<1024, 256>>>();
    k_mix <<<1024, 256>>>();
    k_invH<<<1024, 256>>>();
    k_invW<<<dim3(256, 2, 4), 256>>>(out);
}